// round 15
// baseline (speedup 1.0000x reference)
#include <cuda_runtime.h>
#include <cuda_fp16.h>
#include <cstdint>

#define NB 2
#define NT 2048
#define ND 1024
#define NH 16
#define NDH 64
#define MTOT (NB*NT)   // 4096

// ---------------------------------------------------------------------------
// Scratch (__device__ globals; allocation-free rule). All 16-bit storage fp16.
// ---------------------------------------------------------------------------
__device__ float g_v[NB*NH*NT*NDH];          // [b,h,t,dh] fp32 (pre-transpose)

__device__ __half g_x16[MTOT*ND];            // x as fp16; later attn-out fp16
__device__ __half g_wthi[4*ND*ND];           // transposed split weights [z][n][k]
__device__ __half g_wtlo[4*ND*ND];

// post-rope operands for attention (Q, K single fp16; S = qh x kh)
__device__ __half g_qhi[NB*NH*NT*NDH];       // [b,h,t,dh]
__device__ __half g_khi[NB*NH*NT*NDH];
__device__ __half g_vt[NB*NH*NT*NDH];        // [b,h,dh,t] single fp16

__device__ float4 g_rope[NT*32];             // (c1,s1,c2,s2) per (t,j)

// ---------------------------------------------------------------------------
// PTX helpers: base-target-safe (mma.sync / cp.async / ldmatrix; NO tcgen05)
// ---------------------------------------------------------------------------
__device__ __forceinline__ uint32_t smem_u32(const void* p) {
    uint32_t a;
    asm("{ .reg .u64 t; cvta.to.shared.u64 t, %1; cvt.u32.u64 %0, t; }"
        : "=r"(a) : "l"(p));
    return a;
}
#define CP_ASYNC16(saddr, gptr) \
    asm volatile("cp.async.cg.shared.global [%0], [%1], 16;" \
                 :: "r"(saddr), "l"(gptr) : "memory")
#define CP_COMMIT() asm volatile("cp.async.commit_group;" ::: "memory")
template<int N>
__device__ __forceinline__ void cp_wait() {
    asm volatile("cp.async.wait_group %0;" :: "n"(N) : "memory");
}
// fp16 HMMA, fp32 accumulate
__device__ __forceinline__ void mma16816(float* d,
        uint32_t a0, uint32_t a1, uint32_t a2, uint32_t a3,
        uint32_t b0, uint32_t b1) {
    asm volatile(
        "mma.sync.aligned.m16n8k16.row.col.f32.f16.f16.f32 "
        "{%0,%1,%2,%3}, {%4,%5,%6,%7}, {%8,%9}, {%0,%1,%2,%3};"
        : "+f"(d[0]), "+f"(d[1]), "+f"(d[2]), "+f"(d[3])
        : "r"(a0), "r"(a1), "r"(a2), "r"(a3), "r"(b0), "r"(b1));
}
__device__ __forceinline__ void ldsm_x4(uint32_t& r0, uint32_t& r1,
                                        uint32_t& r2, uint32_t& r3, uint32_t addr) {
    asm volatile("ldmatrix.sync.aligned.m8n8.x4.shared.b16 {%0,%1,%2,%3}, [%4];"
                 : "=r"(r0), "=r"(r1), "=r"(r2), "=r"(r3) : "r"(addr));
}
__device__ __forceinline__ uint32_t lds32(const char* base, int elem) {
    return *(const uint32_t*)(base + elem * 2);
}
__device__ __forceinline__ uint32_t packhf(float lo, float hi) {
    __half2 h = __floats2half2_rn(lo, hi);
    return *reinterpret_cast<uint32_t*>(&h);
}
__device__ __forceinline__ float hfx2_lo(uint32_t u) {
    __half2 h = *reinterpret_cast<__half2*>(&u);
    return __low2float(h);
}
__device__ __forceinline__ float hfx2_hi(uint32_t u) {
    __half2 h = *reinterpret_cast<__half2*>(&u);
    return __high2float(h);
}

#define SWZ128(o) ((o) ^ (((o) >> 3) & 0x70))

// ---------------------------------------------------------------------------
// fp32 -> fp16 convert (input x)
// ---------------------------------------------------------------------------
__global__ void tofp16_kernel(const float* __restrict__ src,
                              __half* __restrict__ dst, int n)
{
    int i = blockIdx.x * blockDim.x + threadIdx.x;
    if (i < n) dst[i] = __float2half_rn(src[i]);
}

// ---------------------------------------------------------------------------
// Transpose + split all 4 weights: W[k][n] -> T[z][n][k] (hi/lo fp16)
// ---------------------------------------------------------------------------
__global__ void wsplit_kernel(const float* __restrict__ w0, const float* __restrict__ w1,
                              const float* __restrict__ w2, const float* __restrict__ w3)
{
    __shared__ float tile[32][33];
    int z = blockIdx.z;
    const float* W = (z == 0) ? w0 : (z == 1) ? w1 : (z == 2) ? w2 : w3;
    int k0 = blockIdx.y * 32, n0 = blockIdx.x * 32;
    int tx = threadIdx.x, ty = threadIdx.y;
    #pragma unroll
    for (int i = 0; i < 4; i++)
        tile[ty + i*8][tx] = W[(k0 + ty + i*8) * ND + n0 + tx];
    __syncthreads();
    #pragma unroll
    for (int i = 0; i < 4; i++) {
        float v = tile[tx][ty + i*8];
        __half h = __float2half_rn(v);
        int idx = z*ND*ND + (n0 + ty + i*8) * ND + (k0 + tx);
        g_wthi[idx] = h;
        g_wtlo[idx] = __float2half_rn(v - __half2float(h));
    }
}

// ---------------------------------------------------------------------------
// RoPE trig table
// ---------------------------------------------------------------------------
__global__ void rope_table()
{
    int idx = blockIdx.x * blockDim.x + threadIdx.x;
    if (idx >= NT*32) return;
    int t = idx >> 5, j = idx & 31;
    const double LN1E4 = 9.210340371976184;
    double e1 = (double)(j & ~1) / 64.0;
    double e2 = (double)((j & ~1) + 32) / 64.0;
    double a1 = (double)t * exp(-e1 * LN1E4);
    double a2 = (double)t * exp(-e2 * LN1E4);
    float4 r;
    r.x = (float)cos(a1); r.y = (float)sin(a1);
    r.z = (float)cos(a2); r.w = (float)sin(a2);
    g_rope[idx] = r;
}

// ---------------------------------------------------------------------------
// HMMA 2-term fp16 GEMM: C = A @ (Wh + Wl) + bias   (A single fp16)
// 3 smem tiles (A, Bhi, Blo), double-buffered = 61440 B; 2 CTAs/SM.
// MODE 0: z=0 -> RoPE -> g_qhi; z=1 -> RoPE -> g_khi; z=2 -> g_v fp32
// MODE 1: z=3 (wo) -> OutP fp32 [b,t,d]
// ---------------------------------------------------------------------------
#define BK 32
#define STRIDE 40                       // 32 + 8 pad (conflict-free lds32)
#define TILE_B (128*STRIDE*2)           // 10240 B
#define GBUF_B (3*TILE_B)               // 30720 B
#define SMEM_GEMM (2*GBUF_B)            // 61440 B

template<int MODE>
__global__ __launch_bounds__(256, 2)
void hmma_gemm(const __half* __restrict__ A_g,
               const float* __restrict__ b0, const float* __restrict__ b1,
               const float* __restrict__ b2,
               float* __restrict__ OutP)
{
    extern __shared__ __align__(16) char smem[];
    const int tid = threadIdx.x;
    const int wid = tid >> 5;
    const int lane = tid & 31;
    const int lq = lane >> 2;
    const int lr = lane & 3;

    const int z = (MODE == 0) ? blockIdx.z : 3;
    const __half* Bhi_g = g_wthi + (size_t)z * ND * ND;
    const __half* Blo_g = g_wtlo + (size_t)z * ND * ND;
    const float* bias = (MODE == 0) ? ((z == 0) ? b0 : (z == 1) ? b1 : b2) : b0;

    const int m0 = blockIdx.y * 128, n0 = blockIdx.x * 128;
    const int wm = (wid >> 1) * 32;
    const int wn = (wid & 1) * 64;

    // loader: 2 threads/row, 32 B each
    const int lrow = tid >> 1, lhalf = tid & 1;
    const __half* gA    = A_g    + (size_t)(m0 + lrow) * ND + lhalf * 16;
    const __half* gB_hi = Bhi_g + (size_t)(n0 + lrow) * ND + lhalf * 16;
    const __half* gB_lo = Blo_g + (size_t)(n0 + lrow) * ND + lhalf * 16;
    const uint32_t sldst = smem_u32(smem) + (lrow * STRIDE + lhalf * 16) * 2;

    float acc[2][8][4];
    #pragma unroll
    for (int mt = 0; mt < 2; mt++)
        #pragma unroll
        for (int nt = 0; nt < 8; nt++)
            #pragma unroll
            for (int i = 0; i < 4; i++) acc[mt][nt][i] = 0.f;

    auto issue = [&](int chunk, int buf) {
        const uint32_t s = sldst + buf * GBUF_B;
        const int g = chunk * BK;
        #pragma unroll
        for (int i = 0; i < 2; i++) {
            CP_ASYNC16(s + 0*TILE_B + i*16, gA    + g + i*8);
            CP_ASYNC16(s + 1*TILE_B + i*16, gB_hi + g + i*8);
            CP_ASYNC16(s + 2*TILE_B + i*16, gB_lo + g + i*8);
        }
        CP_COMMIT();
    };

    issue(0, 0);
    issue(1, 1);

    const int NCHUNK = ND / BK;             // 32
    for (int c = 0; c < NCHUNK; c++) {
        const int buf = c & 1;
        if (c < NCHUNK - 1) cp_wait<1>(); else cp_wait<0>();
        __syncthreads();

        const char* base = smem + buf * GBUF_B;
        const char* sA  = base;
        const char* sBh = base + 1*TILE_B;
        const char* sBl = base + 2*TILE_B;

        #pragma unroll
        for (int ks = 0; ks < 2; ks++) {
            const int kc = ks * 16 + lr * 2;
            uint32_t a[2][4];
            #pragma unroll
            for (int mt = 0; mt < 2; mt++) {
                const int r0 = wm + mt * 16 + lq;
                a[mt][0] = lds32(sA, r0*STRIDE + kc);
                a[mt][1] = lds32(sA, (r0+8)*STRIDE + kc);
                a[mt][2] = lds32(sA, r0*STRIDE + kc + 8);
                a[mt][3] = lds32(sA, (r0+8)*STRIDE + kc + 8);
            }
            #pragma unroll
            for (int nt = 0; nt < 8; nt++) {
                const int nr = wn + nt * 8 + lq;
                uint32_t bh0 = lds32(sBh, nr*STRIDE + kc);
                uint32_t bh1 = lds32(sBh, nr*STRIDE + kc + 8);
                uint32_t bl0 = lds32(sBl, nr*STRIDE + kc);
                uint32_t bl1 = lds32(sBl, nr*STRIDE + kc + 8);
                #pragma unroll
                for (int mt = 0; mt < 2; mt++) {
                    mma16816(acc[mt][nt], a[mt][0], a[mt][1], a[mt][2], a[mt][3], bh0, bh1);
                    mma16816(acc[mt][nt], a[mt][0], a[mt][1], a[mt][2], a[mt][3], bl0, bl1);
                }
            }
        }
        __syncthreads();
        if (c + 2 < NCHUNK) issue(c + 2, buf);
    }

    // ------------------------- epilogue -------------------------
    const int nh0 = (n0 + wn) >> 6;     // head index (warp spans one 64-col head)
    if (MODE == 1) {
        #pragma unroll
        for (int mt = 0; mt < 2; mt++)
            #pragma unroll
            for (int nt = 0; nt < 8; nt++) {
                const int n = n0 + wn + nt * 8 + lr * 2;
                const float bx = bias[n], by = bias[n + 1];
                const int row0 = m0 + wm + mt * 16 + lq;
                #pragma unroll
                for (int half = 0; half < 2; half++) {
                    const int m = row0 + half * 8;
                    float2 v;
                    v.x = acc[mt][nt][half*2 + 0] + bx;
                    v.y = acc[mt][nt][half*2 + 1] + by;
                    *(float2*)&OutP[(size_t)m * ND + n] = v;
                }
            }
    } else if (z == 2) {
        // V: plain fp32 [b,h,t,dh]
        #pragma unroll
        for (int mt = 0; mt < 2; mt++)
            #pragma unroll
            for (int nt = 0; nt < 8; nt++) {
                const int n = n0 + wn + nt * 8 + lr * 2;
                const float bx = bias[n], by = bias[n + 1];
                const int row0 = m0 + wm + mt * 16 + lq;
                #pragma unroll
                for (int half = 0; half < 2; half++) {
                    const int m = row0 + half * 8;
                    const int bi = m >> 11, t = m & (NT - 1);
                    float2 v;
                    v.x = acc[mt][nt][half*2 + 0] + bx;
                    v.y = acc[mt][nt][half*2 + 1] + by;
                    *(float2*)&g_v[(((size_t)(bi*NH + nh0)*NT + t) << 6) + (n & 63)] = v;
                }
            }
    } else {
        // Q or K: fused RoPE -> single fp16 (cols j and j+32 register-local)
        __half* dhi = (z == 0) ? g_qhi : g_khi;
        #pragma unroll
        for (int mt = 0; mt < 2; mt++)
            #pragma unroll
            for (int half = 0; half < 2; half++) {
                const int m = m0 + wm + mt * 16 + lq + half * 8;
                const int bi = m >> 11, t = m & (NT - 1);
                __half* rh = dhi + (((size_t)(bi*NH + nh0)*NT + t) << 6);
                #pragma unroll
                for (int nt = 0; nt < 4; nt++) {
                    const int j = nt * 8 + lr * 2;
                    const int n = n0 + wn + j;
                    float r1[2], r2[2];
                    #pragma unroll
                    for (int e = 0; e < 2; e++) {
                        float a1 = acc[mt][nt][half*2 + e]     + bias[n + e];
                        float a2 = acc[mt][nt + 4][half*2 + e] + bias[n + 32 + e];
                        float4 cs = g_rope[t*32 + j + e];
                        r1[e] = a1*cs.x - a2*cs.y;
                        r2[e] = a2*cs.z + a1*cs.w;
                    }
                    *(uint32_t*)(rh + j)      = packhf(r1[0], r1[1]);
                    *(uint32_t*)(rh + j + 32) = packhf(r2[0], r2[1]);
                }
            }
    }
}

// ---------------------------------------------------------------------------
// V transpose: g_v [b,h,t,dh] fp32 -> g_vt [b,h,dh,t] single fp16
// ---------------------------------------------------------------------------
__global__ __launch_bounds__(256) void vtrans()
{
    __shared__ float tile[64][65];
    const int bh = blockIdx.y, tb = blockIdx.x * 64;
    const int tid = threadIdx.x;
    const int r = tid >> 2, c4 = (tid & 3) * 16;
    const float* src = g_v + ((size_t)bh*NT + tb + r) * 64 + c4;
    #pragma unroll
    for (int i = 0; i < 4; i++) {
        float4 v = *(const float4*)(src + i*4);
        tile[r][c4+i*4+0] = v.x; tile[r][c4+i*4+1] = v.y;
        tile[r][c4+i*4+2] = v.z; tile[r][c4+i*4+3] = v.w;
    }
    __syncthreads();
    const int dh = tid >> 2, t4 = (tid & 3) * 16;
    size_t ob = ((size_t)bh*64 + dh) * NT + tb + t4;
    #pragma unroll
    for (int i = 0; i < 8; i++) {
        float a = tile[t4 + 2*i][dh], b = tile[t4 + 2*i + 1][dh];
        *(__half2*)(g_vt + ob + 2*i) =
            __halves2half2(__float2half_rn(a), __float2half_rn(b));
    }
}

// ---------------------------------------------------------------------------
// HMMA flash attention, causal.
// S = qh x kh (1-term, 4 MMAs/nb); PV = (ph + pl) x V (8 MMAs/no).
// Smem: K, V tiles (2 x 8 KB) double-buffered = 32 KB; 2 CTAs/SM.
// Epilogue writes attn-out as SINGLE fp16 into g_x16.
// ---------------------------------------------------------------------------
#define AT_TILE_B 8192
#define AT_BUF_B  (2*AT_TILE_B)     // 16384
#define SMEM_ATTN (2*AT_BUF_B)      // 32768

__global__ __launch_bounds__(256, 2)
void attn_hmma()
{
    extern __shared__ __align__(128) char asmem[];
    const uint32_t sbase = smem_u32(asmem);
    const int tid = threadIdx.x, wid = tid >> 5, lane = tid & 31;
    const int lq = lane >> 2, lr = lane & 3;
    const int bx = gridDim.x - 1 - blockIdx.x;
    const int bh = blockIdx.y;
    const int qb = bx * 128;
    const int last = 2*bx + 1;

    const size_t hb = (size_t)bh * NT * 64;
    const __half* Qh = g_qhi + hb;
    const __half* Kh = g_khi + hb;
    const __half* Vt = g_vt + hb;      // [dh][t]

    uint32_t qh[4][4];
    {
        const size_t r0 = (size_t)(qb + wid*16 + lq);
        #pragma unroll
        for (int kb = 0; kb < 4; kb++) {
            const int d0 = kb*16 + lr*2;
            qh[kb][0] = *(const uint32_t*)(Qh + r0*64 + d0);
            qh[kb][1] = *(const uint32_t*)(Qh + (r0+8)*64 + d0);
            qh[kb][2] = *(const uint32_t*)(Qh + r0*64 + d0 + 8);
            qh[kb][3] = *(const uint32_t*)(Qh + (r0+8)*64 + d0 + 8);
        }
    }

    float O[8][4];
    #pragma unroll
    for (int i = 0; i < 8; i++)
        #pragma unroll
        for (int c = 0; c < 4; c++) O[i][c] = 0.f;
    float m0 = -1e30f, m1 = -1e30f, l0 = 0.f, l1 = 0.f;

    const int lrow = tid >> 2;
    const int lcb  = (tid & 3) * 2;

    auto issue = [&](int kt, int buf) {
        const uint32_t sb = sbase + buf * AT_BUF_B;
        #pragma unroll
        for (int c2 = 0; c2 < 2; c2++) {
            const int c = lcb + c2;
            const uint32_t sw = SWZ128((uint32_t)(lrow*128 + c*16));
            const size_t gk = ((size_t)(kt*64 + lrow))*64 + c*8;
            const size_t gv = (size_t)lrow*NT + kt*64 + c*8;
            CP_ASYNC16(sb + 0*AT_TILE_B + sw, Kh + gk);
            CP_ASYNC16(sb + 1*AT_TILE_B + sw, Vt + gv);
        }
        CP_COMMIT();
    };

    issue(0, 0);
    const int rg0 = qb + wid*16 + lq;
    const int trow = lane & 7;
    const int tcol = (lane >> 3) * 16;

    for (int kt = 0; kt <= last; kt++) {
        if (kt < last) issue(kt + 1, (kt + 1) & 1);
        if (kt < last) cp_wait<1>(); else cp_wait<0>();
        __syncthreads();

        const bool active = (kt*64 <= qb + wid*16 + 15);
        if (active) {
            const uint32_t sb = sbase + (kt & 1) * AT_BUF_B;
            const uint32_t off1 = SWZ128((uint32_t)(trow*128 + tcol));
            const uint32_t off2 = SWZ128((uint32_t)(trow*128 + 64 + tcol));

            float S[8][4];
            #pragma unroll
            for (int nb = 0; nb < 8; nb++) {
                uint32_t ka[4], kb_[4];
                const uint32_t ro = (uint32_t)(nb * 8 * 128);
                ldsm_x4(ka[0], ka[1], ka[2], ka[3], sb + 0*AT_TILE_B + ro + off1);
                ldsm_x4(kb_[0], kb_[1], kb_[2], kb_[3], sb + 0*AT_TILE_B + ro + off2);
                S[nb][0] = S[nb][1] = S[nb][2] = S[nb][3] = 0.f;
                mma16816(S[nb], qh[0][0], qh[0][1], qh[0][2], qh[0][3], ka[0], ka[1]);
                mma16816(S[nb], qh[1][0], qh[1][1], qh[1][2], qh[1][3], ka[2], ka[3]);
                mma16816(S[nb], qh[2][0], qh[2][1], qh[2][2], qh[2][3], kb_[0], kb_[1]);
                mma16816(S[nb], qh[3][0], qh[3][1], qh[3][2], qh[3][3], kb_[2], kb_[3]);
            }

            if (kt*64 + 63 > qb + wid*16) {
                #pragma unroll
                for (int nb = 0; nb < 8; nb++) {
                    const int cg = kt*64 + nb*8 + lr*2;
                    S[nb][0] = (cg     > rg0    ) ? -1e30f : S[nb][0] * 0.125f;
                    S[nb][1] = (cg + 1 > rg0    ) ? -1e30f : S[nb][1] * 0.125f;
                    S[nb][2] = (cg     > rg0 + 8) ? -1e30f : S[nb][2] * 0.125f;
                    S[nb][3] = (cg + 1 > rg0 + 8) ? -1e30f : S[nb][3] * 0.125f;
                }
            } else {
                #pragma unroll
                for (int nb = 0; nb < 8; nb++)
                    #pragma unroll
                    for (int c = 0; c < 4; c++) S[nb][c] *= 0.125f;
            }

            float mx0 = -1e30f, mx1 = -1e30f;
            #pragma unroll
            for (int nb = 0; nb < 8; nb++) {
                mx0 = fmaxf(mx0, fmaxf(S[nb][0], S[nb][1]));
                mx1 = fmaxf(mx1, fmaxf(S[nb][2], S[nb][3]));
            }
            mx0 = fmaxf(mx0, __shfl_xor_sync(0xffffffffu, mx0, 1));
            mx0 = fmaxf(mx0, __shfl_xor_sync(0xffffffffu, mx0, 2));
            mx1 = fmaxf(mx1, __shfl_xor_sync(0xffffffffu, mx1, 1));
            mx1 = fmaxf(mx1, __shfl_xor_sync(0xffffffffu, mx1, 2));
            const float mn0 = fmaxf(m0, mx0), mn1 = fmaxf(m1, mx1);
            const float al0 = __expf(m0 - mn0), al1 = __expf(m1 - mn1);
            float s0 = 0.f, s1 = 0.f;
            #pragma unroll
            for (int nb = 0; nb < 8; nb++) {
                S[nb][0] = __expf(S[nb][0] - mn0); s0 += S[nb][0];
                S[nb][1] = __expf(S[nb][1] - mn0); s0 += S[nb][1];
                S[nb][2] = __expf(S[nb][2] - mn1); s1 += S[nb][2];
                S[nb][3] = __expf(S[nb][3] - mn1); s1 += S[nb][3];
            }
            s0 += __shfl_xor_sync(0xffffffffu, s0, 1);
            s0 += __shfl_xor_sync(0xffffffffu, s0, 2);
            s1 += __shfl_xor_sync(0xffffffffu, s1, 1);
            s1 += __shfl_xor_sync(0xffffffffu, s1, 2);
            l0 = l0*al0 + s0; l1 = l1*al1 + s1;
            m0 = mn0; m1 = mn1;
            #pragma unroll
            for (int i = 0; i < 8; i++) {
                O[i][0] *= al0; O[i][1] *= al0;
                O[i][2] *= al1; O[i][3] *= al1;
            }

            // P fragments (fp16 split: P exact to ~2^-22)
            uint32_t ph[4][4], pl[4][4];
            #pragma unroll
            for (int kb = 0; kb < 4; kb++) {
                const int nA = 2*kb, nBd = 2*kb + 1;
                ph[kb][0] = packhf(S[nA][0],  S[nA][1]);
                ph[kb][1] = packhf(S[nA][2],  S[nA][3]);
                ph[kb][2] = packhf(S[nBd][0], S[nBd][1]);
                ph[kb][3] = packhf(S[nBd][2], S[nBd][3]);
                pl[kb][0] = packhf(S[nA][0]  - hfx2_lo(ph[kb][0]), S[nA][1]  - hfx2_hi(ph[kb][0]));
                pl[kb][1] = packhf(S[nA][2]  - hfx2_lo(ph[kb][1]), S[nA][3]  - hfx2_hi(ph[kb][1]));
                pl[kb][2] = packhf(S[nBd][0] - hfx2_lo(ph[kb][2]), S[nBd][1] - hfx2_hi(ph[kb][2]));
                pl[kb][3] = packhf(S[nBd][2] - hfx2_lo(ph[kb][3]), S[nBd][3] - hfx2_hi(ph[kb][3]));
            }

            // O += (ph + pl) x V(single fp16)  — 8 MMAs per no
            #pragma unroll
            for (int no = 0; no < 8; no++) {
                uint32_t va[4], vb[4];
                const uint32_t ro = (uint32_t)(no * 8 * 128);
                ldsm_x4(va[0], va[1], va[2], va[3], sb + 1*AT_TILE_B + ro + off1);
                ldsm_x4(vb[0], vb[1], vb[2], vb[3], sb + 1*AT_TILE_B + ro + off2);
                mma16816(O[no], ph[0][0], ph[0][1], ph[0][2], ph[0][3], va[0], va[1]);
                mma16816(O[no], ph[1][0], ph[1][1], ph[1][2], ph[1][3], va[2], va[3]);
                mma16816(O[no], ph[2][0], ph[2][1], ph[2][2], ph[2][3], vb[0], vb[1]);
                mma16816(O[no], ph[3][0], ph[3][1], ph[3][2], ph[3][3], vb[2], vb[3]);
                mma16816(O[no], pl[0][0], pl[0][1], pl[0][2], pl[0][3], va[0], va[1]);
                mma16816(O[no], pl[1][0], pl[1][1], pl[1][2], pl[1][3], va[2], va[3]);
                mma16816(O[no], pl[2][0], pl[2][1], pl[2][2], pl[2][3], vb[0], vb[1]);
                mma16816(O[no], pl[3][0], pl[3][1], pl[3][2], pl[3][3], vb[2], vb[3]);
            }
        }
        __syncthreads();
    }

    // ---- epilogue: normalize, single fp16 write -> g_x16 [b,t,d] ----
    const int bi = bh >> 4, h = bh & 15;
    const int t0 = qb + wid*16 + lq;
    const float i0 = 1.f / l0, i1 = 1.f / l1;
    #pragma unroll
    for (int no = 0; no < 8; no++) {
        const int dh = no*8 + lr*2;
        const size_t e0 = ((size_t)(bi*NT + t0))*ND + h*64 + dh;
        const size_t e1 = ((size_t)(bi*NT + t0 + 8))*ND + h*64 + dh;
        *(uint32_t*)(g_x16 + e0) = packhf(O[no][0]*i0, O[no][1]*i0);
        *(uint32_t*)(g_x16 + e1) = packhf(O[no][2]*i1, O[no][3]*i1);
    }
}

// ---------------------------------------------------------------------------
// Launch. Inputs: x, mask, wq, bq, wk, bk, wv, bv, wo, bo.
// ---------------------------------------------------------------------------
extern "C" void kernel_launch(void* const* d_in, const int* in_sizes, int n_in,
                              void* d_out, int out_size)
{
    const float* x  = (const float*)d_in[0];
    const float* wq = (const float*)d_in[2];
    const float* bq = (const float*)d_in[3];
    const float* wk = (const float*)d_in[4];
    const float* bk = (const float*)d_in[5];
    const float* wv = (const float*)d_in[6];
    const float* bv = (const float*)d_in[7];
    const float* wo = (const float*)d_in[8];
    const float* bo = (const float*)d_in[9];
    float* out = (float*)d_out;

    __half* x16;
    cudaGetSymbolAddress((void**)&x16, g_x16);

    cudaFuncSetAttribute(hmma_gemm<0>,
                         cudaFuncAttributeMaxDynamicSharedMemorySize, SMEM_GEMM);
    cudaFuncSetAttribute(hmma_gemm<1>,
                         cudaFuncAttributeMaxDynamicSharedMemorySize, SMEM_GEMM);
    cudaFuncSetAttribute(attn_hmma,
                         cudaFuncAttributeMaxDynamicSharedMemorySize, SMEM_ATTN);

    // 1) x -> fp16; transpose+split weights; rope trig table
    tofp16_kernel<<<(MTOT*ND)/256, 256>>>(x, x16, MTOT*ND);
    wsplit_kernel<<<dim3(32, 32, 4), dim3(32, 8)>>>(wq, wk, wv, wo);
    rope_table<<<(NT*32)/256, 256>>>();

    // 2) fused QKV projections (2-term) + RoPE (Q,K single fp16 / V fp32)
    hmma_gemm<0><<<dim3(8, 32, 3), 256, SMEM_GEMM>>>(x16, bq, bk, bv, nullptr);

    // 3) transpose V -> single fp16 [b,h,dh,t]
    vtrans<<<dim3(NT/64, NB*NH), 256>>>();

    // 4) HMMA flash attention -> single fp16 attn-out in g_x16
    attn_hmma<<<dim3(NT/128, NB*NH), 256, SMEM_ATTN>>>();

    // 5) out-projection (2-term) -> d_out
    hmma_gemm<1><<<dim3(8, 32, 1), 256, SMEM_GEMM>>>(x16, bo, bo, bo, out);
}

// round 16
// speedup vs baseline: 1.5361x; 1.5361x over previous
#include <cuda_runtime.h>
#include <cuda_fp16.h>
#include <cstdint>

#define NB 2
#define NT 2048
#define ND 1024
#define NH 16
#define NDH 64
#define MTOT (NB*NT)   // 4096

// ---------------------------------------------------------------------------
// Scratch (__device__ globals; allocation-free rule). All 16-bit storage fp16.
// ---------------------------------------------------------------------------
__device__ float g_v[NB*NH*NT*NDH];          // [b,h,t,dh] fp32 (pre-transpose)

__device__ __half g_x16[MTOT*ND];            // x as fp16; later attn-out fp16
__device__ __half g_wthi[4*ND*ND];           // transposed split weights [z][n][k]
__device__ __half g_wtlo[4*ND*ND];

// post-rope operands for attention (Q, K single fp16; S = qh x kh)
__device__ __half g_qhi[NB*NH*NT*NDH];       // [b,h,t,dh]
__device__ __half g_khi[NB*NH*NT*NDH];
__device__ __half g_vt[NB*NH*NT*NDH];        // [b,h,dh,t] single fp16

__device__ float4 g_rope[NT*32];             // (c1,s1,c2,s2) per (t,j)

// ---------------------------------------------------------------------------
// PTX helpers: base-target-safe (mma.sync / cp.async / ldmatrix; NO tcgen05)
// ---------------------------------------------------------------------------
__device__ __forceinline__ uint32_t smem_u32(const void* p) {
    uint32_t a;
    asm("{ .reg .u64 t; cvta.to.shared.u64 t, %1; cvt.u32.u64 %0, t; }"
        : "=r"(a) : "l"(p));
    return a;
}
#define CP_ASYNC16(saddr, gptr) \
    asm volatile("cp.async.cg.shared.global [%0], [%1], 16;" \
                 :: "r"(saddr), "l"(gptr) : "memory")
#define CP_COMMIT() asm volatile("cp.async.commit_group;" ::: "memory")
template<int N>
__device__ __forceinline__ void cp_wait() {
    asm volatile("cp.async.wait_group %0;" :: "n"(N) : "memory");
}
// fp16 HMMA, fp32 accumulate
__device__ __forceinline__ void mma16816(float* d,
        uint32_t a0, uint32_t a1, uint32_t a2, uint32_t a3,
        uint32_t b0, uint32_t b1) {
    asm volatile(
        "mma.sync.aligned.m16n8k16.row.col.f32.f16.f16.f32 "
        "{%0,%1,%2,%3}, {%4,%5,%6,%7}, {%8,%9}, {%0,%1,%2,%3};"
        : "+f"(d[0]), "+f"(d[1]), "+f"(d[2]), "+f"(d[3])
        : "r"(a0), "r"(a1), "r"(a2), "r"(a3), "r"(b0), "r"(b1));
}
__device__ __forceinline__ void ldsm_x4(uint32_t& r0, uint32_t& r1,
                                        uint32_t& r2, uint32_t& r3, uint32_t addr) {
    asm volatile("ldmatrix.sync.aligned.m8n8.x4.shared.b16 {%0,%1,%2,%3}, [%4];"
                 : "=r"(r0), "=r"(r1), "=r"(r2), "=r"(r3) : "r"(addr));
}
__device__ __forceinline__ uint32_t lds32(const char* base, int elem) {
    return *(const uint32_t*)(base + elem * 2);
}
__device__ __forceinline__ uint32_t packhf(float lo, float hi) {
    __half2 h = __floats2half2_rn(lo, hi);
    return *reinterpret_cast<uint32_t*>(&h);
}
__device__ __forceinline__ float hfx2_lo(uint32_t u) {
    __half2 h = *reinterpret_cast<__half2*>(&u);
    return __low2float(h);
}
__device__ __forceinline__ float hfx2_hi(uint32_t u) {
    __half2 h = *reinterpret_cast<__half2*>(&u);
    return __high2float(h);
}

#define SWZ128(o) ((o) ^ (((o) >> 3) & 0x70))

// ---------------------------------------------------------------------------
// fp32 -> fp16 convert (input x)
// ---------------------------------------------------------------------------
__global__ void tofp16_kernel(const float* __restrict__ src,
                              __half* __restrict__ dst, int n)
{
    int i = blockIdx.x * blockDim.x + threadIdx.x;
    if (i < n) dst[i] = __float2half_rn(src[i]);
}

// ---------------------------------------------------------------------------
// Transpose + split all 4 weights: W[k][n] -> T[z][n][k] (hi/lo fp16)
// ---------------------------------------------------------------------------
__global__ void wsplit_kernel(const float* __restrict__ w0, const float* __restrict__ w1,
                              const float* __restrict__ w2, const float* __restrict__ w3)
{
    __shared__ float tile[32][33];
    int z = blockIdx.z;
    const float* W = (z == 0) ? w0 : (z == 1) ? w1 : (z == 2) ? w2 : w3;
    int k0 = blockIdx.y * 32, n0 = blockIdx.x * 32;
    int tx = threadIdx.x, ty = threadIdx.y;
    #pragma unroll
    for (int i = 0; i < 4; i++)
        tile[ty + i*8][tx] = W[(k0 + ty + i*8) * ND + n0 + tx];
    __syncthreads();
    #pragma unroll
    for (int i = 0; i < 4; i++) {
        float v = tile[tx][ty + i*8];
        __half h = __float2half_rn(v);
        int idx = z*ND*ND + (n0 + ty + i*8) * ND + (k0 + tx);
        g_wthi[idx] = h;
        g_wtlo[idx] = __float2half_rn(v - __half2float(h));
    }
}

// ---------------------------------------------------------------------------
// RoPE trig table
// ---------------------------------------------------------------------------
__global__ void rope_table()
{
    int idx = blockIdx.x * blockDim.x + threadIdx.x;
    if (idx >= NT*32) return;
    int t = idx >> 5, j = idx & 31;
    const double LN1E4 = 9.210340371976184;
    double e1 = (double)(j & ~1) / 64.0;
    double e2 = (double)((j & ~1) + 32) / 64.0;
    double a1 = (double)t * exp(-e1 * LN1E4);
    double a2 = (double)t * exp(-e2 * LN1E4);
    float4 r;
    r.x = (float)cos(a1); r.y = (float)sin(a1);
    r.z = (float)cos(a2); r.w = (float)sin(a2);
    g_rope[idx] = r;
}

// ---------------------------------------------------------------------------
// HMMA 2-term fp16 GEMM: C = A @ (Wh + Wl) + bias   (A single fp16)
// 3 smem tiles (A, Bhi, Blo), double-buffered = 61440 B; 2 CTAs/SM.
// MODE 0: z=0 -> RoPE -> g_qhi; z=1 -> RoPE -> g_khi; z=2 -> g_v fp32
// MODE 1: z=3 (wo) -> OutP fp32 [b,t,d]
// ---------------------------------------------------------------------------
#define BK 32
#define STRIDE 40                       // 32 + 8 pad (conflict-free lds32)
#define TILE_B (128*STRIDE*2)           // 10240 B
#define GBUF_B (3*TILE_B)               // 30720 B
#define SMEM_GEMM (2*GBUF_B)            // 61440 B

template<int MODE>
__global__ __launch_bounds__(256, 2)
void hmma_gemm(const __half* __restrict__ A_g,
               const float* __restrict__ b0, const float* __restrict__ b1,
               const float* __restrict__ b2,
               float* __restrict__ OutP)
{
    extern __shared__ __align__(16) char smem[];
    const int tid = threadIdx.x;
    const int wid = tid >> 5;
    const int lane = tid & 31;
    const int lq = lane >> 2;
    const int lr = lane & 3;

    const int z = (MODE == 0) ? blockIdx.z : 3;
    const __half* Bhi_g = g_wthi + (size_t)z * ND * ND;
    const __half* Blo_g = g_wtlo + (size_t)z * ND * ND;
    const float* bias = (MODE == 0) ? ((z == 0) ? b0 : (z == 1) ? b1 : b2) : b0;

    const int m0 = blockIdx.y * 128, n0 = blockIdx.x * 128;
    const int wm = (wid >> 1) * 32;
    const int wn = (wid & 1) * 64;

    // loader: 2 threads/row, 32 B each
    const int lrow = tid >> 1, lhalf = tid & 1;
    const __half* gA    = A_g    + (size_t)(m0 + lrow) * ND + lhalf * 16;
    const __half* gB_hi = Bhi_g + (size_t)(n0 + lrow) * ND + lhalf * 16;
    const __half* gB_lo = Blo_g + (size_t)(n0 + lrow) * ND + lhalf * 16;
    const uint32_t sldst = smem_u32(smem) + (lrow * STRIDE + lhalf * 16) * 2;

    float acc[2][8][4];
    #pragma unroll
    for (int mt = 0; mt < 2; mt++)
        #pragma unroll
        for (int nt = 0; nt < 8; nt++)
            #pragma unroll
            for (int i = 0; i < 4; i++) acc[mt][nt][i] = 0.f;

    auto issue = [&](int chunk, int buf) {
        const uint32_t s = sldst + buf * GBUF_B;
        const int g = chunk * BK;
        #pragma unroll
        for (int i = 0; i < 2; i++) {
            CP_ASYNC16(s + 0*TILE_B + i*16, gA    + g + i*8);
            CP_ASYNC16(s + 1*TILE_B + i*16, gB_hi + g + i*8);
            CP_ASYNC16(s + 2*TILE_B + i*16, gB_lo + g + i*8);
        }
        CP_COMMIT();
    };

    issue(0, 0);
    issue(1, 1);

    const int NCHUNK = ND / BK;             // 32
    for (int c = 0; c < NCHUNK; c++) {
        const int buf = c & 1;
        if (c < NCHUNK - 1) cp_wait<1>(); else cp_wait<0>();
        __syncthreads();

        const char* base = smem + buf * GBUF_B;
        const char* sA  = base;
        const char* sBh = base + 1*TILE_B;
        const char* sBl = base + 2*TILE_B;

        #pragma unroll
        for (int ks = 0; ks < 2; ks++) {
            const int kc = ks * 16 + lr * 2;
            uint32_t a[2][4];
            #pragma unroll
            for (int mt = 0; mt < 2; mt++) {
                const int r0 = wm + mt * 16 + lq;
                a[mt][0] = lds32(sA, r0*STRIDE + kc);
                a[mt][1] = lds32(sA, (r0+8)*STRIDE + kc);
                a[mt][2] = lds32(sA, r0*STRIDE + kc + 8);
                a[mt][3] = lds32(sA, (r0+8)*STRIDE + kc + 8);
            }
            #pragma unroll
            for (int nt = 0; nt < 8; nt++) {
                const int nr = wn + nt * 8 + lq;
                uint32_t bh0 = lds32(sBh, nr*STRIDE + kc);
                uint32_t bh1 = lds32(sBh, nr*STRIDE + kc + 8);
                uint32_t bl0 = lds32(sBl, nr*STRIDE + kc);
                uint32_t bl1 = lds32(sBl, nr*STRIDE + kc + 8);
                #pragma unroll
                for (int mt = 0; mt < 2; mt++) {
                    mma16816(acc[mt][nt], a[mt][0], a[mt][1], a[mt][2], a[mt][3], bh0, bh1);
                    mma16816(acc[mt][nt], a[mt][0], a[mt][1], a[mt][2], a[mt][3], bl0, bl1);
                }
            }
        }
        __syncthreads();
        if (c + 2 < NCHUNK) issue(c + 2, buf);
    }

    // ------------------------- epilogue -------------------------
    const int nh0 = (n0 + wn) >> 6;     // head index (warp spans one 64-col head)
    if (MODE == 1) {
        #pragma unroll
        for (int mt = 0; mt < 2; mt++)
            #pragma unroll
            for (int nt = 0; nt < 8; nt++) {
                const int n = n0 + wn + nt * 8 + lr * 2;
                const float bx = bias[n], by = bias[n + 1];
                const int row0 = m0 + wm + mt * 16 + lq;
                #pragma unroll
                for (int half = 0; half < 2; half++) {
                    const int m = row0 + half * 8;
                    float2 v;
                    v.x = acc[mt][nt][half*2 + 0] + bx;
                    v.y = acc[mt][nt][half*2 + 1] + by;
                    *(float2*)&OutP[(size_t)m * ND + n] = v;
                }
            }
    } else if (z == 2) {
        // V: plain fp32 [b,h,t,dh]
        #pragma unroll
        for (int mt = 0; mt < 2; mt++)
            #pragma unroll
            for (int nt = 0; nt < 8; nt++) {
                const int n = n0 + wn + nt * 8 + lr * 2;
                const float bx = bias[n], by = bias[n + 1];
                const int row0 = m0 + wm + mt * 16 + lq;
                #pragma unroll
                for (int half = 0; half < 2; half++) {
                    const int m = row0 + half * 8;
                    const int bi = m >> 11, t = m & (NT - 1);
                    float2 v;
                    v.x = acc[mt][nt][half*2 + 0] + bx;
                    v.y = acc[mt][nt][half*2 + 1] + by;
                    *(float2*)&g_v[(((size_t)(bi*NH + nh0)*NT + t) << 6) + (n & 63)] = v;
                }
            }
    } else {
        // Q or K: fused RoPE -> single fp16 (cols j and j+32 register-local)
        __half* dhi = (z == 0) ? g_qhi : g_khi;
        #pragma unroll
        for (int mt = 0; mt < 2; mt++)
            #pragma unroll
            for (int half = 0; half < 2; half++) {
                const int m = m0 + wm + mt * 16 + lq + half * 8;
                const int bi = m >> 11, t = m & (NT - 1);
                __half* rh = dhi + (((size_t)(bi*NH + nh0)*NT + t) << 6);
                #pragma unroll
                for (int nt = 0; nt < 4; nt++) {
                    const int j = nt * 8 + lr * 2;
                    const int n = n0 + wn + j;
                    float r1[2], r2[2];
                    #pragma unroll
                    for (int e = 0; e < 2; e++) {
                        float a1 = acc[mt][nt][half*2 + e]     + bias[n + e];
                        float a2 = acc[mt][nt + 4][half*2 + e] + bias[n + 32 + e];
                        float4 cs = g_rope[t*32 + j + e];
                        r1[e] = a1*cs.x - a2*cs.y;
                        r2[e] = a2*cs.z + a1*cs.w;
                    }
                    *(uint32_t*)(rh + j)      = packhf(r1[0], r1[1]);
                    *(uint32_t*)(rh + j + 32) = packhf(r2[0], r2[1]);
                }
            }
    }
}

// ---------------------------------------------------------------------------
// V transpose: g_v [b,h,t,dh] fp32 -> g_vt [b,h,dh,t] single fp16
// ---------------------------------------------------------------------------
__global__ __launch_bounds__(256) void vtrans()
{
    __shared__ float tile[64][65];
    const int bh = blockIdx.y, tb = blockIdx.x * 64;
    const int tid = threadIdx.x;
    const int r = tid >> 2, c4 = (tid & 3) * 16;
    const float* src = g_v + ((size_t)bh*NT + tb + r) * 64 + c4;
    #pragma unroll
    for (int i = 0; i < 4; i++) {
        float4 v = *(const float4*)(src + i*4);
        tile[r][c4+i*4+0] = v.x; tile[r][c4+i*4+1] = v.y;
        tile[r][c4+i*4+2] = v.z; tile[r][c4+i*4+3] = v.w;
    }
    __syncthreads();
    const int dh = tid >> 2, t4 = (tid & 3) * 16;
    size_t ob = ((size_t)bh*64 + dh) * NT + tb + t4;
    #pragma unroll
    for (int i = 0; i < 8; i++) {
        float a = tile[t4 + 2*i][dh], b = tile[t4 + 2*i + 1][dh];
        *(__half2*)(g_vt + ob + 2*i) =
            __halves2half2(__float2half_rn(a), __float2half_rn(b));
    }
}

// ---------------------------------------------------------------------------
// HMMA flash attention, causal.
// S = qh x kh (1-term, 4 MMAs/nb); PV = (ph + pl) x V (8 MMAs/no).
// Smem: K, V tiles (2 x 8 KB) double-buffered = 32 KB; 2 CTAs/SM.
// Epilogue writes attn-out as SINGLE fp16 into g_x16.
// ---------------------------------------------------------------------------
#define AT_TILE_B 8192
#define AT_BUF_B  (2*AT_TILE_B)     // 16384
#define SMEM_ATTN (2*AT_BUF_B)      // 32768

__global__ __launch_bounds__(256, 2)
void attn_hmma()
{
    extern __shared__ __align__(128) char asmem[];
    const uint32_t sbase = smem_u32(asmem);
    const int tid = threadIdx.x, wid = tid >> 5, lane = tid & 31;
    const int lq = lane >> 2, lr = lane & 3;
    const int bx = gridDim.x - 1 - blockIdx.x;
    const int bh = blockIdx.y;
    const int qb = bx * 128;
    const int last = 2*bx + 1;

    const size_t hb = (size_t)bh * NT * 64;
    const __half* Qh = g_qhi + hb;
    const __half* Kh = g_khi + hb;
    const __half* Vt = g_vt + hb;      // [dh][t]

    uint32_t qh[4][4];
    {
        const size_t r0 = (size_t)(qb + wid*16 + lq);
        #pragma unroll
        for (int kb = 0; kb < 4; kb++) {
            const int d0 = kb*16 + lr*2;
            qh[kb][0] = *(const uint32_t*)(Qh + r0*64 + d0);
            qh[kb][1] = *(const uint32_t*)(Qh + (r0+8)*64 + d0);
            qh[kb][2] = *(const uint32_t*)(Qh + r0*64 + d0 + 8);
            qh[kb][3] = *(const uint32_t*)(Qh + (r0+8)*64 + d0 + 8);
        }
    }

    float O[8][4];
    #pragma unroll
    for (int i = 0; i < 8; i++)
        #pragma unroll
        for (int c = 0; c < 4; c++) O[i][c] = 0.f;
    float m0 = -1e30f, m1 = -1e30f, l0 = 0.f, l1 = 0.f;

    const int lrow = tid >> 2;
    const int lcb  = (tid & 3) * 2;

    auto issue = [&](int kt, int buf) {
        const uint32_t sb = sbase + buf * AT_BUF_B;
        #pragma unroll
        for (int c2 = 0; c2 < 2; c2++) {
            const int c = lcb + c2;
            const uint32_t sw = SWZ128((uint32_t)(lrow*128 + c*16));
            const size_t gk = ((size_t)(kt*64 + lrow))*64 + c*8;
            const size_t gv = (size_t)lrow*NT + kt*64 + c*8;
            CP_ASYNC16(sb + 0*AT_TILE_B + sw, Kh + gk);
            CP_ASYNC16(sb + 1*AT_TILE_B + sw, Vt + gv);
        }
        CP_COMMIT();
    };

    issue(0, 0);
    const int rg0 = qb + wid*16 + lq;
    const int trow = lane & 7;
    const int tcol = (lane >> 3) * 16;

    for (int kt = 0; kt <= last; kt++) {
        if (kt < last) issue(kt + 1, (kt + 1) & 1);
        if (kt < last) cp_wait<1>(); else cp_wait<0>();
        __syncthreads();

        const bool active = (kt*64 <= qb + wid*16 + 15);
        if (active) {
            const uint32_t sb = sbase + (kt & 1) * AT_BUF_B;
            const uint32_t off1 = SWZ128((uint32_t)(trow*128 + tcol));
            const uint32_t off2 = SWZ128((uint32_t)(trow*128 + 64 + tcol));

            float S[8][4];
            #pragma unroll
            for (int nb = 0; nb < 8; nb++) {
                uint32_t ka[4], kb_[4];
                const uint32_t ro = (uint32_t)(nb * 8 * 128);
                ldsm_x4(ka[0], ka[1], ka[2], ka[3], sb + 0*AT_TILE_B + ro + off1);
                ldsm_x4(kb_[0], kb_[1], kb_[2], kb_[3], sb + 0*AT_TILE_B + ro + off2);
                S[nb][0] = S[nb][1] = S[nb][2] = S[nb][3] = 0.f;
                mma16816(S[nb], qh[0][0], qh[0][1], qh[0][2], qh[0][3], ka[0], ka[1]);
                mma16816(S[nb], qh[1][0], qh[1][1], qh[1][2], qh[1][3], ka[2], ka[3]);
                mma16816(S[nb], qh[2][0], qh[2][1], qh[2][2], qh[2][3], kb_[0], kb_[1]);
                mma16816(S[nb], qh[3][0], qh[3][1], qh[3][2], qh[3][3], kb_[2], kb_[3]);
            }

            if (kt*64 + 63 > qb + wid*16) {
                #pragma unroll
                for (int nb = 0; nb < 8; nb++) {
                    const int cg = kt*64 + nb*8 + lr*2;
                    S[nb][0] = (cg     > rg0    ) ? -1e30f : S[nb][0] * 0.125f;
                    S[nb][1] = (cg + 1 > rg0    ) ? -1e30f : S[nb][1] * 0.125f;
                    S[nb][2] = (cg     > rg0 + 8) ? -1e30f : S[nb][2] * 0.125f;
                    S[nb][3] = (cg + 1 > rg0 + 8) ? -1e30f : S[nb][3] * 0.125f;
                }
            } else {
                #pragma unroll
                for (int nb = 0; nb < 8; nb++)
                    #pragma unroll
                    for (int c = 0; c < 4; c++) S[nb][c] *= 0.125f;
            }

            float mx0 = -1e30f, mx1 = -1e30f;
            #pragma unroll
            for (int nb = 0; nb < 8; nb++) {
                mx0 = fmaxf(mx0, fmaxf(S[nb][0], S[nb][1]));
                mx1 = fmaxf(mx1, fmaxf(S[nb][2], S[nb][3]));
            }
            mx0 = fmaxf(mx0, __shfl_xor_sync(0xffffffffu, mx0, 1));
            mx0 = fmaxf(mx0, __shfl_xor_sync(0xffffffffu, mx0, 2));
            mx1 = fmaxf(mx1, __shfl_xor_sync(0xffffffffu, mx1, 1));
            mx1 = fmaxf(mx1, __shfl_xor_sync(0xffffffffu, mx1, 2));
            const float mn0 = fmaxf(m0, mx0), mn1 = fmaxf(m1, mx1);
            const float al0 = __expf(m0 - mn0), al1 = __expf(m1 - mn1);
            float s0 = 0.f, s1 = 0.f;
            #pragma unroll
            for (int nb = 0; nb < 8; nb++) {
                S[nb][0] = __expf(S[nb][0] - mn0); s0 += S[nb][0];
                S[nb][1] = __expf(S[nb][1] - mn0); s0 += S[nb][1];
                S[nb][2] = __expf(S[nb][2] - mn1); s1 += S[nb][2];
                S[nb][3] = __expf(S[nb][3] - mn1); s1 += S[nb][3];
            }
            s0 += __shfl_xor_sync(0xffffffffu, s0, 1);
            s0 += __shfl_xor_sync(0xffffffffu, s0, 2);
            s1 += __shfl_xor_sync(0xffffffffu, s1, 1);
            s1 += __shfl_xor_sync(0xffffffffu, s1, 2);
            l0 = l0*al0 + s0; l1 = l1*al1 + s1;
            m0 = mn0; m1 = mn1;
            #pragma unroll
            for (int i = 0; i < 8; i++) {
                O[i][0] *= al0; O[i][1] *= al0;
                O[i][2] *= al1; O[i][3] *= al1;
            }

            // P fragments (fp16 split: P exact to ~2^-22)
            uint32_t ph[4][4], pl[4][4];
            #pragma unroll
            for (int kb = 0; kb < 4; kb++) {
                const int nA = 2*kb, nBd = 2*kb + 1;
                ph[kb][0] = packhf(S[nA][0],  S[nA][1]);
                ph[kb][1] = packhf(S[nA][2],  S[nA][3]);
                ph[kb][2] = packhf(S[nBd][0], S[nBd][1]);
                ph[kb][3] = packhf(S[nBd][2], S[nBd][3]);
                pl[kb][0] = packhf(S[nA][0]  - hfx2_lo(ph[kb][0]), S[nA][1]  - hfx2_hi(ph[kb][0]));
                pl[kb][1] = packhf(S[nA][2]  - hfx2_lo(ph[kb][1]), S[nA][3]  - hfx2_hi(ph[kb][1]));
                pl[kb][2] = packhf(S[nBd][0] - hfx2_lo(ph[kb][2]), S[nBd][1] - hfx2_hi(ph[kb][2]));
                pl[kb][3] = packhf(S[nBd][2] - hfx2_lo(ph[kb][3]), S[nBd][3] - hfx2_hi(ph[kb][3]));
            }

            // O += (ph + pl) x V(single fp16)  — 8 MMAs per no
            #pragma unroll
            for (int no = 0; no < 8; no++) {
                uint32_t va[4], vb[4];
                const uint32_t ro = (uint32_t)(no * 8 * 128);
                ldsm_x4(va[0], va[1], va[2], va[3], sb + 1*AT_TILE_B + ro + off1);
                ldsm_x4(vb[0], vb[1], vb[2], vb[3], sb + 1*AT_TILE_B + ro + off2);
                mma16816(O[no], ph[0][0], ph[0][1], ph[0][2], ph[0][3], va[0], va[1]);
                mma16816(O[no], ph[1][0], ph[1][1], ph[1][2], ph[1][3], va[2], va[3]);
                mma16816(O[no], ph[2][0], ph[2][1], ph[2][2], ph[2][3], vb[0], vb[1]);
                mma16816(O[no], ph[3][0], ph[3][1], ph[3][2], ph[3][3], vb[2], vb[3]);
                mma16816(O[no], pl[0][0], pl[0][1], pl[0][2], pl[0][3], va[0], va[1]);
                mma16816(O[no], pl[1][0], pl[1][1], pl[1][2], pl[1][3], va[2], va[3]);
                mma16816(O[no], pl[2][0], pl[2][1], pl[2][2], pl[2][3], vb[0], vb[1]);
                mma16816(O[no], pl[3][0], pl[3][1], pl[3][2], pl[3][3], vb[2], vb[3]);
            }
        }
        __syncthreads();
    }

    // ---- epilogue: normalize, single fp16 write -> g_x16 [b,t,d] ----
    const int bi = bh >> 4, h = bh & 15;
    const int t0 = qb + wid*16 + lq;
    const float i0 = 1.f / l0, i1 = 1.f / l1;
    #pragma unroll
    for (int no = 0; no < 8; no++) {
        const int dh = no*8 + lr*2;
        const size_t e0 = ((size_t)(bi*NT + t0))*ND + h*64 + dh;
        const size_t e1 = ((size_t)(bi*NT + t0 + 8))*ND + h*64 + dh;
        *(uint32_t*)(g_x16 + e0) = packhf(O[no][0]*i0, O[no][1]*i0);
        *(uint32_t*)(g_x16 + e1) = packhf(O[no][2]*i1, O[no][3]*i1);
    }
}

// ---------------------------------------------------------------------------
// Launch. Inputs: x, mask, wq, bq, wk, bk, wv, bv, wo, bo.
// ---------------------------------------------------------------------------
extern "C" void kernel_launch(void* const* d_in, const int* in_sizes, int n_in,
                              void* d_out, int out_size)
{
    const float* x  = (const float*)d_in[0];
    const float* wq = (const float*)d_in[2];
    const float* bq = (const float*)d_in[3];
    const float* wk = (const float*)d_in[4];
    const float* bk = (const float*)d_in[5];
    const float* wv = (const float*)d_in[6];
    const float* bv = (const float*)d_in[7];
    const float* wo = (const float*)d_in[8];
    const float* bo = (const float*)d_in[9];
    float* out = (float*)d_out;

    __half* x16;
    cudaGetSymbolAddress((void**)&x16, g_x16);

    cudaFuncSetAttribute(hmma_gemm<0>,
                         cudaFuncAttributeMaxDynamicSharedMemorySize, SMEM_GEMM);
    cudaFuncSetAttribute(hmma_gemm<1>,
                         cudaFuncAttributeMaxDynamicSharedMemorySize, SMEM_GEMM);
    cudaFuncSetAttribute(attn_hmma,
                         cudaFuncAttributeMaxDynamicSharedMemorySize, SMEM_ATTN);

    // 1) x -> fp16; transpose+split weights; rope trig table
    tofp16_kernel<<<(MTOT*ND)/256, 256>>>(x, x16, MTOT*ND);
    wsplit_kernel<<<dim3(32, 32, 4), dim3(32, 8)>>>(wq, wk, wv, wo);
    rope_table<<<(NT*32)/256, 256>>>();

    // 2) fused QKV projections (2-term) + RoPE (Q,K single fp16 / V fp32)
    hmma_gemm<0><<<dim3(8, 32, 3), 256, SMEM_GEMM>>>(x16, bq, bk, bv, nullptr);

    // 3) transpose V -> single fp16 [b,h,dh,t]
    vtrans<<<dim3(NT/64, NB*NH), 256>>>();

    // 4) HMMA flash attention -> single fp16 attn-out in g_x16
    attn_hmma<<<dim3(NT/128, NB*NH), 256, SMEM_ATTN>>>();

    // 5) out-projection (2-term) -> d_out
    hmma_gemm<1><<<dim3(8, 32, 1), 256, SMEM_GEMM>>>(x16, bo, bo, bo, out);
}